// round 17
// baseline (speedup 1.0000x reference)
#include <cuda_runtime.h>
#include <cuda_fp16.h>
#include <cstdint>
#include <stdint.h>
#include <math.h>

#define T_    4096
#define D_    1024
#define E_    8
#define CAP_  1024
#define MLP_  4096

// ---------------- device scratch ----------------
__device__ float g_h[(size_t)T_ * D_];
__device__ __half g_hh[(size_t)(T_ + 128) * D_];   // fp16 h + zero sentinel rows
__device__ float g_expo[(size_t)E_ * CAP_ * D_];
__device__ float g_probs[T_ * 8];
__device__ unsigned char g_maskb[T_];
__device__ int   g_slottok[E_ * CAP_];
__device__ int   g_slotof[E_ * T_];
__device__ float g_cw[T_ * 8];
__device__ int   g_nsel[E_];
__device__ float2 g_csn[4 * CAP_ * 32];

__device__ __half g_q[4ull * CAP_ * D_];
__device__ __half g_k[4ull * CAP_ * D_];
__device__ __half g_v[4ull * CAP_ * D_];
__device__ __half g_a[4ull * CAP_ * D_];
__device__ __half g_f[4ull * CAP_ * MLP_];

#define WQ_OFF 0ull
#define WK_OFF 4194304ull
#define WV_OFF 8388608ull
#define WO_OFF 12582912ull
#define W1_OFF 16777216ull
#define W2_OFF 33554432ull
#define WT_TOT 50331648ull
__device__ __half g_wt[WT_TOT];

// ---------------- helpers ----------------
__device__ __forceinline__ uint32_t smem_u32(const void* p) {
    uint32_t a;
    asm("{ .reg .u64 t; cvta.to.shared.u64 t, %1; cvt.u32.u64 %0, t; }" : "=r"(a) : "l"(p));
    return a;
}
__device__ __forceinline__ void cp_async16(uint32_t saddr, const void* gptr) {
    asm volatile("cp.async.cg.shared.global [%0], [%1], 16;" :: "r"(saddr), "l"(gptr));
}
#define CP_COMMIT() asm volatile("cp.async.commit_group;")
#define CP_WAIT(n)  asm volatile("cp.async.wait_group %0;" :: "n"(n))

__device__ __forceinline__ uint32_t h2_u32(__half2 h) {
    return *reinterpret_cast<uint32_t*>(&h);
}
__device__ __forceinline__ float gelu_f(float x) {
    float x3 = x * x * x;
    return 0.5f * x * (1.f + tanhf(0.7978845608028654f * (x + 0.044715f * x3)));
}
__device__ __forceinline__ void mma16816(float* d, const uint32_t* a, const uint32_t* b) {
    asm volatile(
        "mma.sync.aligned.m16n8k16.row.col.f32.f16.f16.f32 "
        "{%0,%1,%2,%3}, {%4,%5,%6,%7}, {%8,%9}, {%0,%1,%2,%3};"
        : "+f"(d[0]), "+f"(d[1]), "+f"(d[2]), "+f"(d[3])
        : "r"(a[0]), "r"(a[1]), "r"(a[2]), "r"(a[3]), "r"(b[0]), "r"(b[1]));
}
__device__ __forceinline__ uint32_t lds_frag(const __half* base, int r, int c) {
    int ch = c >> 3;
    int sw = ch ^ ((r >> 1) & 3);
    return *(const uint32_t*)(base + r * 32 + sw * 8 + (c & 7));
}
__device__ __forceinline__ uint32_t lds_sw64(const __half* base, int r, int c) {
    int ch = c >> 3;
    int sw = ch ^ (r & 7);
    return *(const uint32_t*)(base + r * 64 + sw * 8 + (c & 7));
}

// ---------------- embedding (also zero sentinel rows of g_hh) ----------------
__global__ void embed_kernel(const int* __restrict__ ids, const float* __restrict__ ew) {
    int t = blockIdx.x, tid = threadIdx.x;
    if (t >= T_) {
        ((__half2*)(g_hh + (size_t)t * D_))[2 * tid] = __halves2half2(__half(0.f), __half(0.f));
        ((__half2*)(g_hh + (size_t)t * D_))[2 * tid + 1] = __halves2half2(__half(0.f), __half(0.f));
        return;
    }
    float4 v = ((const float4*)(ew + (size_t)ids[t] * D_))[tid];
    ((float4*)(g_h + (size_t)t * D_))[tid] = v;
    __half2* d = (__half2*)(g_hh + (size_t)t * D_) + 2 * tid;
    d[0] = __halves2half2(__float2half_rn(v.x), __float2half_rn(v.y));
    d[1] = __halves2half2(__float2half_rn(v.z), __float2half_rn(v.w));
}

// ---------------- router (hop 0 only) ----------------
__global__ void router_kernel(const float* __restrict__ rw) {
    int gw = (blockIdx.x * blockDim.x + threadIdx.x) >> 5;
    int lane = threadIdx.x & 31;
    if (gw >= T_) return;
    const float* hr = g_h + (size_t)gw * D_;
    float acc[9];
#pragma unroll
    for (int e = 0; e < 9; e++) acc[e] = 0.f;
    for (int d = lane; d < D_; d += 32) {
        float hv = hr[d];
#pragma unroll
        for (int e = 0; e < 9; e++) acc[e] = fmaf(hv, rw[e * D_ + d], acc[e]);
    }
#pragma unroll
    for (int e = 0; e < 9; e++)
#pragma unroll
        for (int o = 16; o > 0; o >>= 1) acc[e] += __shfl_xor_sync(0xffffffffu, acc[e], o);
    if (lane == 0) {
        float mx = acc[0];
#pragma unroll
        for (int e = 1; e < 9; e++) mx = fmaxf(mx, acc[e]);
        float ex[9], s = 0.f;
#pragma unroll
        for (int e = 0; e < 9; e++) { ex[e] = expf(acc[e] - mx); s += ex[e]; }
        float inv = 1.f / s;
        int a1 = 0; float v1 = acc[0];
#pragma unroll
        for (int e = 1; e < 9; e++) if (acc[e] > v1) { v1 = acc[e]; a1 = e; }
        int a2 = -1; float v2 = -3.0e38f;
#pragma unroll
        for (int e = 0; e < 9; e++) if (e != a1 && acc[e] > v2) { v2 = acc[e]; a2 = e; }
        unsigned char m = 0;
        if (a1 < 8) m |= (unsigned char)(1 << a1);
        if (a2 < 8) m |= (unsigned char)(1 << a2);
        g_maskb[gw] = m;
#pragma unroll
        for (int e = 0; e < 8; e++) g_probs[gw * 8 + e] = ex[e] * inv;
    }
}

// ---------------- capacity select (+ RoPE angle table for attn experts) ----------------
__global__ void __launch_bounds__(1024) capacity_kernel() {
    int e = blockIdx.x, tid = threadIdx.x;
    __shared__ unsigned long long keys[T_];
    __shared__ int s_count;
    if (tid == 0) s_count = 0;
    __syncthreads();
    int local = 0;
    for (int t = tid; t < T_; t += 1024) {
        unsigned long long key = 0ull;
        if (g_maskb[t] & (1 << e)) {
            unsigned pb = __float_as_uint(g_probs[t * 8 + e]);
            key = ((unsigned long long)pb << 32) | (unsigned)(0xFFFFFFFFu - (unsigned)t);
            local++;
        }
        keys[t] = key;
    }
#pragma unroll
    for (int o = 16; o > 0; o >>= 1) local += __shfl_xor_sync(0xffffffffu, local, o);
    if ((tid & 31) == 0) atomicAdd(&s_count, local);
    __syncthreads();
    for (int k = 2; k <= T_; k <<= 1)
        for (int j = k >> 1; j > 0; j >>= 1) {
            for (int i = tid; i < T_; i += 1024) {
                int ixj = i ^ j;
                if (ixj > i) {
                    unsigned long long a = keys[i], b = keys[ixj];
                    bool desc = ((i & k) == 0);
                    if (desc ? (a < b) : (a > b)) { keys[i] = b; keys[ixj] = a; }
                }
            }
            __syncthreads();
        }
    int nsel = min(s_count, CAP_);
    if (tid == 0) g_nsel[e] = nsel;
    for (int t = tid; t < T_; t += 1024) { g_slotof[e * T_ + t] = -1; g_cw[t * 8 + e] = 0.f; }
    __syncthreads();
    int c = tid;
    int tok = T_;                         // sentinel: zero row of g_hh
    if (c < nsel) {
        unsigned long long key = keys[c];
        tok = (int)(0xFFFFFFFFu - (unsigned)(key & 0xFFFFFFFFull));
        g_slottok[e * CAP_ + c] = tok;
        g_slotof[e * T_ + tok] = c;
        g_cw[tok * 8 + e] = __uint_as_float((unsigned)(key >> 32));
    } else {
        g_slottok[e * CAP_ + c] = T_;
    }
    // RoPE angles for attention experts (even e)
    if ((e & 1) == 0) {
        int g = e >> 1;
        float pos = (float)tok;           // padded rows: angle irrelevant (zero Q/K)
        float2* dst = g_csn + ((size_t)g * CAP_ + c) * 32;
#pragma unroll 4
        for (int j = 0; j < 32; j++) {
            float invf = exp2f(-(float)(2 * j) * (13.287712379549449f / 64.0f));
            float ang = pos * invf;
            dst[j] = make_float2(cosf(ang), sinf(ang));
        }
    }
}

// ---------------- weight transpose + fp16: 64x64 vectorized ----------------
__global__ void wconv_kernel(const float* __restrict__ W, __half* __restrict__ Th,
                             int K, int N, int perm) {
    __shared__ float s[64][65];
    int z = blockIdx.z;
    size_t base = (size_t)z * K * N;
    int n0 = blockIdx.x * 64, k0 = blockIdx.y * 64;
    int tid = threadIdx.x;
#pragma unroll
    for (int i = 0; i < 4; i++) {
        int linear = tid + i * 256;
        int k = linear >> 4, c4 = (linear & 15) << 2;
        float4 v = *(const float4*)(W + base + (size_t)(k0 + k) * N + n0 + c4);
        s[c4 + 0][k] = v.x; s[c4 + 1][k] = v.y;
        s[c4 + 2][k] = v.z; s[c4 + 3][k] = v.w;
    }
    __syncthreads();
#pragma unroll
    for (int i = 0; i < 2; i++) {
        int linear = tid + i * 256;
        int n = linear >> 3, k8 = (linear & 7) << 3;
        __half hh[8];
#pragma unroll
        for (int j = 0; j < 8; j++) hh[j] = __float2half_rn(s[n][k8 + j]);
        int ng = n0 + n, nn = ng;
        if (perm) {
            int j = ng & 63;
            nn = (ng & ~63) | (j < 32 ? (j << 1) : (((j - 32) << 1) | 1));
        }
        *(uint4*)(Th + base + (size_t)nn * K + k0 + k8) = *(uint4*)hh;
    }
}

// ---------------- cp.async 3-stage pipelined fp16 mma.sync GEMM ----------------
#define GSMEM 49152

__device__ __forceinline__ void issue_tile(uint32_t sbase, const __half* __restrict__ g,
                                           int K, int k0, int tid) {
#pragma unroll
    for (int q = 0; q < 2; q++) {
        int i = tid * 2 + q;
        int r = i >> 2, ch = i & 3;
        int sw = ch ^ ((r >> 1) & 3);
        cp_async16(sbase + (uint32_t)(r * 32 + sw * 8) * 2,
                   g + (size_t)r * K + k0 + ch * 8);
    }
}
// indirect A: row r -> g_hh[stok[r]]
__device__ __forceinline__ void issue_tile_ind(uint32_t sbase, const int* __restrict__ stok,
                                               int k0, int tid) {
#pragma unroll
    for (int q = 0; q < 2; q++) {
        int i = tid * 2 + q;
        int r = i >> 2, ch = i & 3;
        int sw = ch ^ ((r >> 1) & 3);
        cp_async16(sbase + (uint32_t)(r * 32 + sw * 8) * 2,
                   g_hh + (size_t)stok[r] * D_ + k0 + ch * 8);
    }
}

// A from g_hh via slot map (K = D_), B from weights
__device__ __forceinline__ void gemm_mma_ind(
    int expert, const __half* __restrict__ B,
    float* Cf, __half* Ch, int N, int act, const float2* __restrict__ csn,
    int bx, int by)
{
    extern __shared__ char gsm[];
    __shared__ int stok[128];
    uint32_t sb = smem_u32(gsm);
    int tid = threadIdx.x, lane = tid & 31, warp = tid >> 5;
    int wm = (warp & 1) * 64, wn = (warp >> 1) * 32;
    int brow = by * 128, bcol = bx * 128;
    if (tid < 128) stok[tid] = g_slottok[expert * CAP_ + brow + tid];
    __syncthreads();
    const __half* pB = B + (size_t)bcol * D_;

    float acc[4][4][4];
#pragma unroll
    for (int i = 0; i < 4; i++)
#pragma unroll
        for (int j = 0; j < 4; j++)
#pragma unroll
            for (int d = 0; d < 4; d++) acc[i][j][d] = 0.f;

    int g = lane >> 2, t4 = lane & 3;
    const int NC = D_ >> 5;

    issue_tile_ind(sb,        stok, 0, tid);
    issue_tile(sb + 8192, pB, D_, 0, tid);
    CP_COMMIT();
    issue_tile_ind(sb + 16384,        stok, 32, tid);
    issue_tile(sb + 16384 + 8192, pB, D_, 32, tid);
    CP_COMMIT();

    for (int c = 0; c < NC; c++) {
        if (c + 2 < NC) {
            uint32_t nb = sb + (uint32_t)((c + 2) % 3) * 16384;
            int k0 = (c + 2) << 5;
            issue_tile_ind(nb,        stok, k0, tid);
            issue_tile(nb + 8192, pB, D_, k0, tid);
        }
        CP_COMMIT();
        CP_WAIT(2);
        __syncthreads();
        const __half* sA = (const __half*)(gsm + (c % 3) * 16384);
        const __half* sB = sA + 4096;
#pragma unroll
        for (int kc = 0; kc < 2; kc++) {
            int cb = kc * 16 + t4 * 2;
            uint32_t bfr[4][2];
#pragma unroll
            for (int tn = 0; tn < 4; tn++) {
                int n = wn + tn * 8 + g;
                bfr[tn][0] = lds_frag(sB, n, cb);
                bfr[tn][1] = lds_frag(sB, n, cb + 8);
            }
#pragma unroll
            for (int tm = 0; tm < 4; tm++) {
                int r = wm + tm * 16 + g;
                uint32_t afr[4];
                afr[0] = lds_frag(sA, r, cb);     afr[1] = lds_frag(sA, r + 8, cb);
                afr[2] = lds_frag(sA, r, cb + 8); afr[3] = lds_frag(sA, r + 8, cb + 8);
#pragma unroll
                for (int tn = 0; tn < 4; tn++)
                    mma16816(acc[tm][tn], afr, bfr[tn]);
            }
        }
        __syncthreads();
    }

#pragma unroll
    for (int tm = 0; tm < 4; tm++) {
        int r = brow + wm + tm * 16 + g;
#pragma unroll
        for (int tn = 0; tn < 4; tn++) {
            int c = bcol + wn + tn * 8 + t4 * 2;
            float v0 = acc[tm][tn][0], v1 = acc[tm][tn][1];
            float v2 = acc[tm][tn][2], v3 = acc[tm][tn][3];
            if (csn) {
                int jj = (c & 63) >> 1;
                float2 csA = csn[r * 32 + jj];
                float2 csB = csn[(r + 8) * 32 + jj];
                float q0 = v0 * csA.x - v1 * csA.y;
                float q1 = v1 * csA.x + v0 * csA.y;
                float q2 = v2 * csB.x - v3 * csB.y;
                float q3 = v3 * csB.x + v2 * csB.y;
                *(__half2*)(Ch + (size_t)r * N + c) =
                    __halves2half2(__float2half_rn(q0), __float2half_rn(q1));
                *(__half2*)(Ch + (size_t)(r + 8) * N + c) =
                    __halves2half2(__float2half_rn(q2), __float2half_rn(q3));
            } else {
                if (act) { v0 = gelu_f(v0); v1 = gelu_f(v1); v2 = gelu_f(v2); v3 = gelu_f(v3); }
                *(__half2*)(Ch + (size_t)r * N + c) =
                    __halves2half2(__float2half_rn(v0), __float2half_rn(v1));
                *(__half2*)(Ch + (size_t)(r + 8) * N + c) =
                    __halves2half2(__float2half_rn(v2), __float2half_rn(v3));
            }
        }
    }
}

// direct GEMM (A contiguous) for Wo / FFN2
__device__ __forceinline__ void gemm_mma_body(
    const __half* __restrict__ A, const __half* __restrict__ B,
    float* Cf, int N, int K, int bx, int by)
{
    extern __shared__ char gsm[];
    uint32_t sb = smem_u32(gsm);
    int tid = threadIdx.x, lane = tid & 31, warp = tid >> 5;
    int wm = (warp & 1) * 64, wn = (warp >> 1) * 32;
    int brow = by * 128, bcol = bx * 128;
    const __half* pA = A + (size_t)brow * K;
    const __half* pB = B + (size_t)bcol * K;

    float acc[4][4][4];
#pragma unroll
    for (int i = 0; i < 4; i++)
#pragma unroll
        for (int j = 0; j < 4; j++)
#pragma unroll
            for (int d = 0; d < 4; d++) acc[i][j][d] = 0.f;

    int g = lane >> 2, t4 = lane & 3;
    int NC = K >> 5;

    issue_tile(sb,        pA, K, 0, tid);
    issue_tile(sb + 8192, pB, K, 0, tid);
    CP_COMMIT();
    if (NC > 1) {
        issue_tile(sb + 16384,        pA, K, 32, tid);
        issue_tile(sb + 16384 + 8192, pB, K, 32, tid);
    }
    CP_COMMIT();

    for (int c = 0; c < NC; c++) {
        if (c + 2 < NC) {
            uint32_t nb = sb + (uint32_t)((c + 2) % 3) * 16384;
            int k0 = (c + 2) << 5;
            issue_tile(nb,        pA, K, k0, tid);
            issue_tile(nb + 8192, pB, K, k0, tid);
        }
        CP_COMMIT();
        CP_WAIT(2);
        __syncthreads();
        const __half* sA = (const __half*)(gsm + (c % 3) * 16384);
        const __half* sB = sA + 4096;
#pragma unroll
        for (int kc = 0; kc < 2; kc++) {
            int cb = kc * 16 + t4 * 2;
            uint32_t bfr[4][2];
#pragma unroll
            for (int tn = 0; tn < 4; tn++) {
                int n = wn + tn * 8 + g;
                bfr[tn][0] = lds_frag(sB, n, cb);
                bfr[tn][1] = lds_frag(sB, n, cb + 8);
            }
#pragma unroll
            for (int tm = 0; tm < 4; tm++) {
                int r = wm + tm * 16 + g;
                uint32_t afr[4];
                afr[0] = lds_frag(sA, r, cb);     afr[1] = lds_frag(sA, r + 8, cb);
                afr[2] = lds_frag(sA, r, cb + 8); afr[3] = lds_frag(sA, r + 8, cb + 8);
#pragma unroll
                for (int tn = 0; tn < 4; tn++)
                    mma16816(acc[tm][tn], afr, bfr[tn]);
            }
        }
        __syncthreads();
    }

#pragma unroll
    for (int tm = 0; tm < 4; tm++) {
        int r = brow + wm + tm * 16 + g;
#pragma unroll
        for (int tn = 0; tn < 4; tn++) {
            int c = bcol + wn + tn * 8 + t4 * 2;
            *(float2*)(Cf + (size_t)r * N + c) = make_float2(acc[tm][tn][0], acc[tm][tn][1]);
            *(float2*)(Cf + (size_t)(r + 8) * N + c) = make_float2(acc[tm][tn][2], acc[tm][tn][3]);
        }
    }
}

// merged QKV (fused RoPE, indirect A) + FFN1 (indirect A); grid (8, 8, 28)
__global__ void __launch_bounds__(256, 2) gemm_fused1() {
    int z = blockIdx.z;
    if (z < 12) {
        int which = z >> 2, g = z & 3;
        size_t wo = (size_t)which * 4194304ull + (size_t)g * 1048576ull;
        if (which == 0)
            gemm_mma_ind(2 * g, g_wt + wo, (float*)0, g_q + (size_t)g * CAP_ * D_,
                         D_, 0, g_csn + (size_t)g * CAP_ * 32, blockIdx.x, blockIdx.y);
        else if (which == 1)
            gemm_mma_ind(2 * g, g_wt + wo, (float*)0, g_k + (size_t)g * CAP_ * D_,
                         D_, 0, g_csn + (size_t)g * CAP_ * 32, blockIdx.x, blockIdx.y);
        else
            gemm_mma_ind(2 * g, g_wt + wo, (float*)0, g_v + (size_t)g * CAP_ * D_,
                         D_, 0, (const float2*)0, blockIdx.x, blockIdx.y);
    } else {
        int zz = z - 12;
        int g = zz >> 2;
        int bx = ((zz & 3) << 3) + blockIdx.x;
        gemm_mma_ind(2 * g + 1, g_wt + W1_OFF + (size_t)g * D_ * MLP_,
                     (float*)0, g_f + (size_t)g * CAP_ * MLP_,
                     MLP_, 1, (const float2*)0, bx, blockIdx.y);
    }
}

// merged Wo + FFN2
__global__ void __launch_bounds__(256, 2) gemm_fused2() {
    int z = blockIdx.z;
    if (z < 4) {
        int g = z;
        gemm_mma_body(g_a + (size_t)g * CAP_ * D_, g_wt + WO_OFF + (size_t)g * D_ * D_,
                      g_expo + (size_t)(2 * g) * CAP_ * D_, D_, D_, blockIdx.x, blockIdx.y);
    } else {
        int g = z - 4;
        gemm_mma_body(g_f + (size_t)g * CAP_ * MLP_, g_wt + W2_OFF + (size_t)g * MLP_ * D_,
                      g_expo + (size_t)(2 * g + 1) * CAP_ * D_, D_, MLP_, blockIdx.x, blockIdx.y);
    }
}

// ---------------- register-softmax HMMA flash attention ----------------
#define A_Q   0
#define A_K0  16384
#define A_V0  24576
#define A_K1  32768
#define A_V1  40960
#define A_VT  49152
#define ATTN_SMEM 57600

__global__ void __launch_bounds__(256, 2) attn_kernel() {
    int qb = blockIdx.x, hh = blockIdx.y, g = blockIdx.z;
    extern __shared__ char sm[];
    uint32_t sb = smem_u32(sm);
    __half* Qs = (__half*)(sm + A_Q);
    __half* Vt = (__half*)(sm + A_VT);

    int tid = threadIdx.x, lane = tid & 31, warp = tid >> 5;
    int gq = lane >> 2, t4 = lane & 3;
    int wq = warp * 16;

    size_t qoff = ((size_t)(g * CAP_ + qb * 128)) * D_ + hh * 64;
#pragma unroll
    for (int it = 0; it < 4; it++) {
        int idx = tid + it * 256;
        int r = idx >> 3, ch = idx & 7, sw = ch ^ (r & 7);
        cp_async16(sb + A_Q + (uint32_t)(r * 64 + sw * 8) * 2,
                   g_q + qoff + (size_t)r * D_ + ch * 8);
    }
    size_t koff0 = ((size_t)(g * CAP_)) * D_ + hh * 64;
#pragma unroll
    for (int it = 0; it < 2; it++) {
        int idx = tid + it * 256;
        int r = idx >> 3, ch = idx & 7, sw = ch ^ (r & 7);
        uint32_t off = (uint32_t)(r * 64 + sw * 8) * 2;
        cp_async16(sb + A_K0 + off, g_k + koff0 + (size_t)r * D_ + ch * 8);
        cp_async16(sb + A_V0 + off, g_v + koff0 + (size_t)r * D_ + ch * 8);
    }
    CP_COMMIT();

    float m0 = -3.0e38f, m1 = -3.0e38f, l0 = 0.f, l1 = 0.f;
    float o[8][4];
#pragma unroll
    for (int i = 0; i < 8; i++)
#pragma unroll
        for (int j = 0; j < 4; j++) o[i][j] = 0.f;

    for (int kt = 0; kt < 16; kt++) {
        __syncthreads();
        if (kt + 1 < 16) {
            uint32_t kb = sb + (((kt + 1) & 1) ? A_K1 : A_K0);
            uint32_t vb = sb + (((kt + 1) & 1) ? A_V1 : A_V0);
            size_t koff = ((size_t)(g * CAP_ + (kt + 1) * 64)) * D_ + hh * 64;
#pragma unroll
            for (int it = 0; it < 2; it++) {
                int idx = tid + it * 256;
                int r = idx >> 3, ch = idx & 7, sw = ch ^ (r & 7);
                uint32_t off = (uint32_t)(r * 64 + sw * 8) * 2;
                cp_async16(kb + off, g_k + koff + (size_t)r * D_ + ch * 8);
                cp_async16(vb + off, g_v + koff + (size_t)r * D_ + ch * 8);
            }
            CP_COMMIT();
            CP_WAIT(1);
        } else {
            CP_WAIT(0);
        }
        __syncthreads();
        const __half* Ks = (const __half*)(sm + ((kt & 1) ? A_K1 : A_K0));
        const __half* Vs = (const __half*)(sm + ((kt & 1) ? A_V1 : A_V0));

        {
            int r2 = tid >> 3, ch = tid & 7;
            int ka = 2 * r2, kb2 = 2 * r2 + 1;
            uint4 va = *(const uint4*)(Vs + ka * 64 + (ch ^ (ka & 7)) * 8);
            uint4 vb2 = *(const uint4*)(Vs + kb2 * 64 + (ch ^ (kb2 & 7)) * 8);
            const __half* ha = (const __half*)&va;
            const __half* hb = (const __half*)&vb2;
#pragma unroll
            for (int j = 0; j < 8; j++)
                *(__half2*)(Vt + (ch * 8 + j) * 66 + ka) = __halves2half2(ha[j], hb[j]);
        }

        float s[8][4];
#pragma unroll
        for (int i = 0; i < 8; i++)
#pragma unroll
            for (int j = 0; j < 4; j++) s[i][j] = 0.f;
#pragma unroll
        for (int ks = 0; ks < 4; ks++) {
            int cb = ks * 16 + t4 * 2;
            uint32_t afr[4];
            afr[0] = lds_sw64(Qs, wq + gq, cb);     afr[1] = lds_sw64(Qs, wq + gq + 8, cb);
            afr[2] = lds_sw64(Qs, wq + gq, cb + 8); afr[3] = lds_sw64(Qs, wq + gq + 8, cb + 8);
#pragma unroll
            for (int tn = 0; tn < 8; tn++) {
                int n = tn * 8 + gq;
                uint32_t bfr[2];
                bfr[0] = lds_sw64(Ks, n, cb); bfr[1] = lds_sw64(Ks, n, cb + 8);
                mma16816(s[tn], afr, bfr);
            }
        }

        float mx0 = -3.0e38f, mx1 = -3.0e38f;
#pragma unroll
        for (int tn = 0; tn < 8; tn++) {
            s[tn][0] *= 0.125f; s[tn][1] *= 0.125f;
            s[tn][2] *= 0.125f; s[tn][3] *= 0.125f;
            mx0 = fmaxf(mx0, fmaxf(s[tn][0], s[tn][1]));
            mx1 = fmaxf(mx1, fmaxf(s[tn][2], s[tn][3]));
        }
        mx0 = fmaxf(mx0, __shfl_xor_sync(0xffffffffu, mx0, 1));
        mx0 = fmaxf(mx0, __shfl_xor_sync(0xffffffffu, mx0, 2));
        mx1 = fmaxf(mx1, __shfl_xor_sync(0xffffffffu, mx1, 1));
        mx1 = fmaxf(mx1, __shfl_xor_sync(0xffffffffu, mx1, 2));
        float mn0 = fmaxf(m0, mx0), mn1 = fmaxf(m1, mx1);
        float cr0 = __expf(m0 - mn0), cr1 = __expf(m1 - mn1);
        float sum0 = 0.f, sum1 = 0.f;
#pragma unroll
        for (int tn = 0; tn < 8; tn++) {
            s[tn][0] = __expf(s[tn][0] - mn0); s[tn][1] = __expf(s[tn][1] - mn0);
            s[tn][2] = __expf(s[tn][2] - mn1); s[tn][3] = __expf(s[tn][3] - mn1);
            sum0 += s[tn][0] + s[tn][1];
            sum1 += s[tn][2] + s[tn][3];
        }
        sum0 += __shfl_xor_sync(0xffffffffu, sum0, 1);
        sum0 += __shfl_xor_sync(0xffffffffu, sum0, 2);
        sum1 += __shfl_xor_sync(0xffffffffu, sum1, 1);
        sum1 += __shfl_xor_sync(0xffffffffu, sum1, 2);
        l0 = l0 * cr0 + sum0; l1 = l1 * cr1 + sum1;
        m0 = mn0; m1 = mn1;
#pragma unroll
        for (int tn = 0; tn < 8; tn++) {
            o[tn][0] *= cr0; o[tn][1] *= cr0;
            o[tn][2] *= cr1; o[tn][3] *= cr1;
        }

        uint32_t pf[4][4];
#pragma unroll
        for (int ks = 0; ks < 4; ks++) {
            pf[ks][0] = h2_u32(__floats2half2_rn(s[2 * ks][0], s[2 * ks][1]));
            pf[ks][1] = h2_u32(__floats2half2_rn(s[2 * ks][2], s[2 * ks][3]));
            pf[ks][2] = h2_u32(__floats2half2_rn(s[2 * ks + 1][0], s[2 * ks + 1][1]));
            pf[ks][3] = h2_u32(__floats2half2_rn(s[2 * ks + 1][2], s[2 * ks + 1][3]));
        }
        __syncthreads();

#pragma unroll
        for (int ks = 0; ks < 4; ks++) {
#pragma unroll
            for (int tn = 0; tn < 8; tn++) {
                int n = tn * 8 + gq;
                int cb = ks * 16 + t4 * 2;
                uint32_t bfr[2];
                bfr[0] = *(const uint32_t*)(Vt + n * 66 + cb);
                bfr[1] = *(const uint32_t*)(Vt + n * 66 + cb + 8);
                mma16816(o[tn], pf[ks], bfr);
            }
        }
    }

    float inv0 = 1.f / l0, inv1 = 1.f / l1;
    size_t obase = ((size_t)(g * CAP_ + qb * 128)) * D_ + hh * 64;
#pragma unroll
    for (int tn = 0; tn < 8; tn++) {
        int c = tn * 8 + t4 * 2;
        size_t off = obase + (size_t)(wq + gq) * D_ + c;
        *(__half2*)(g_a + off) =
            __halves2half2(__float2half_rn(o[tn][0] * inv0), __float2half_rn(o[tn][1] * inv0));
        off = obase + (size_t)(wq + gq + 8) * D_ + c;
        *(__half2*)(g_a + off) =
            __halves2half2(__float2half_rn(o[tn][2] * inv1), __float2half_rn(o[tn][3] * inv1));
    }
}

// ---------------- fused combine + (router | rmsnorm); also writes fp16 h ----------------
__global__ void __launch_bounds__(256) comb_router_kernel(
    const float* __restrict__ rw, const float* __restrict__ lnw,
    float* __restrict__ out, int last)
{
    int warp = threadIdx.x >> 5, lane = threadIdx.x & 31;
    int t = blockIdx.x * 8 + warp;

    float we_l = 0.f; int se_l = -1;
    if (lane < 8) { we_l = g_cw[t * 8 + lane]; se_l = g_slotof[lane * T_ + t]; }

    float hv[32];
#pragma unroll
    for (int i = 0; i < 32; i++) hv[i] = g_h[(size_t)t * D_ + lane + 32 * i];

    float rho = 0.f;
#pragma unroll
    for (int e = 0; e < 8; e++) {
        int se = __shfl_sync(0xffffffffu, se_l, e);
        float we = __shfl_sync(0xffffffffu, we_l, e);
        if (se >= 0) rho += we;
    }
    float om = 1.f - rho;
#pragma unroll
    for (int i = 0; i < 32; i++) hv[i] *= om;
#pragma unroll
    for (int e = 0; e < 8; e++) {
        int se = __shfl_sync(0xffffffffu, se_l, e);
        float we = __shfl_sync(0xffffffffu, we_l, e);
        if (se >= 0) {
            const float* ev = g_expo + ((size_t)e * CAP_ + se) * D_ + lane;
#pragma unroll
            for (int i = 0; i < 32; i++) hv[i] = fmaf(we, ev[32 * i], hv[i]);
        }
    }

    if (!last) {
#pragma unroll
        for (int i = 0; i < 32; i++) {
            int d = lane + 32 * i;
            g_h[(size_t)t * D_ + d] = hv[i];
            g_hh[(size_t)t * D_ + d] = __float2half_rn(hv[i]);
        }
        float acc[9];
#pragma unroll
        for (int e = 0; e < 9; e++) acc[e] = 0.f;
#pragma unroll
        for (int i = 0; i < 32; i++) {
            float hvv = hv[i];
            int d = lane + 32 * i;
#pragma unroll
            for (int e = 0; e < 9; e++) acc[e] = fmaf(hvv, rw[e * D_ + d], acc[e]);
        }
#pragma unroll
        for (int e = 0; e < 9; e++)
#pragma unroll
            for (int o = 16; o > 0; o >>= 1) acc[e] += __shfl_xor_sync(0xffffffffu, acc[e], o);
        if (lane == 0) {
            float mx = acc[0];
#pragma unroll
            for (int e = 1; e < 9; e++) mx = fmaxf(mx, acc[e]);
            float ex[9], s = 0.f;
#pragma unroll
            for (int e = 0; e < 9; e++) { ex[e] = expf(acc[e] - mx); s += ex[e]; }
            float inv = 1.f / s;
            int a1 = 0; float v1 = acc[0];
#pragma unroll
            for (int e = 1; e < 9; e++) if (acc[e] > v1) { v1 = acc[e]; a1 = e; }
            int a2 = -1; float v2 = -3.0e38f;
#pragma unroll
            for (int e = 0; e < 9; e++) if (e != a1 && acc[e] > v2) { v2 = acc[e]; a2 = e; }
            unsigned char m = 0;
            if (a1 < 8) m |= (unsigned char)(1 << a1);
            if (a2 < 8) m |= (unsigned char)(1 << a2);
            g_maskb[t] = m;
#pragma unroll
            for (int e = 0; e < 8; e++) g_probs[t * 8 + e] = ex[e] * inv;
        }
    } else {
        float ss = 0.f;
#pragma unroll
        for (int i = 0; i < 32; i++) ss += hv[i] * hv[i];
#pragma unroll
        for (int o = 16; o > 0; o >>= 1) ss += __shfl_xor_sync(0xffffffffu, ss, o);
        float sc = rsqrtf(ss / (float)D_ + 1e-6f);
#pragma unroll
        for (int i = 0; i < 32; i++) {
            int d = lane + 32 * i;
            out[(size_t)t * D_ + d] = hv[i] * sc * lnw[d];
        }
    }
}

// ---------------- launch ----------------
extern "C" void kernel_launch(void* const* d_in, const int* in_sizes, int n_in,
                              void* d_out, int out_size) {
    const int*   ids      = (const int*)d_in[0];
    const float* embed_w  = (const float*)d_in[1];
    const float* router_w = (const float*)d_in[2];
    const float* wq       = (const float*)d_in[3];
    const float* wk       = (const float*)d_in[4];
    const float* wv       = (const float*)d_in[5];
    const float* wo       = (const float*)d_in[6];
    const float* w1       = (const float*)d_in[7];
    const float* w2       = (const float*)d_in[8];
    const float* lnw      = (const float*)d_in[9];
    float* out = (float*)d_out;

    __half* p_wt;
    cudaGetSymbolAddress((void**)&p_wt, g_wt);

    cudaFuncSetAttribute(attn_kernel, cudaFuncAttributeMaxDynamicSharedMemorySize, ATTN_SMEM);
    cudaFuncSetAttribute(gemm_fused1, cudaFuncAttributeMaxDynamicSharedMemorySize, GSMEM);
    cudaFuncSetAttribute(gemm_fused2, cudaFuncAttributeMaxDynamicSharedMemorySize, GSMEM);

    wconv_kernel<<<dim3(16, 16, 4), 256>>>(wq, p_wt + WQ_OFF, D_, D_, 1);
    wconv_kernel<<<dim3(16, 16, 4), 256>>>(wk, p_wt + WK_OFF, D_, D_, 1);
    wconv_kernel<<<dim3(16, 16, 4), 256>>>(wv, p_wt + WV_OFF, D_, D_, 0);
    wconv_kernel<<<dim3(16, 16, 4), 256>>>(wo, p_wt + WO_OFF, D_, D_, 0);
    wconv_kernel<<<dim3(64, 16, 4), 256>>>(w1, p_wt + W1_OFF, D_, MLP_, 0);
    wconv_kernel<<<dim3(16, 64, 4), 256>>>(w2, p_wt + W2_OFF, MLP_, D_, 0);

    embed_kernel<<<T_ + 128, 256>>>(ids, embed_w);
    router_kernel<<<T_ / 8, 256>>>(router_w);
    for (int hop = 0; hop < 3; hop++) {
        capacity_kernel<<<E_, 1024>>>();
        gemm_fused1<<<dim3(8, 8, 28), 256, GSMEM>>>();
        attn_kernel<<<dim3(8, 16, 4), 256, ATTN_SMEM>>>();
        gemm_fused2<<<dim3(8, 8, 8), 256, GSMEM>>>();
        if (hop < 2)
            comb_router_kernel<<<T_ / 8, 256>>>(
                router_w + (size_t)(hop + 1) * 9 * D_, (const float*)0, (float*)0, 0);
        else
            comb_router_kernel<<<T_ / 8, 256>>>(
                (const float*)0, lnw, out, 1);
    }
}